// round 8
// baseline (speedup 1.0000x reference)
#include <cuda_runtime.h>
#include <cstdint>

#define NN 100000
#define EE 3200000
#define IN_CH 256
#define HID 64
#define OUTC 32

// ---------------- scratch (no allocations allowed) ----------------
__device__ int   d_is64;                      // 1 if edge_index is int64, else 0
__device__ __align__(16) int   d_row32[EE];   // edge sources as int32
__device__ __align__(16) int   d_col32[EE];   // edge targets as int32
__device__ __align__(16) int   d_cnt[NN];     // in-degree (edges only)
__device__ __align__(16) int   d_off[NN];     // CSR start offsets
__device__ __align__(16) int   d_cur[NN];     // fill cursors
__device__ __align__(16) int   d_erow[EE];    // CSR payload: source node per edge
__device__ __align__(16) float d_dis[NN];
__device__ __align__(16) float d_g1[(size_t)NN * HID];   // dis * (x @ W1)
__device__ __align__(16) float d_g2[(size_t)NN * OUTC];  // dis * (h1 @ W2)

// ---------------- dtype detector: int64 edge_index has all-zero odd words ----------------
__global__ void k_detect(const int* __restrict__ ei_w) {
    int lane = threadIdx.x;  // one warp
    // sample odd words spread over the first EE int32 words (in-bounds for both layouts)
    int nz = 0;
#pragma unroll
    for (int j = 0; j < 8; j++) {
        long long k = (long long)(lane * 8 + j) * (EE / 512);  // < EE/2
        int w = ei_w[2 * k + 1];
        nz |= w;
    }
    unsigned any = __ballot_sync(0xffffffffu, nz != 0);
    if (lane == 0) d_is64 = (any == 0u) ? 1 : 0;
}

// ---------------- convert edge_index to int32 row/col ----------------
__global__ void k_cvt(const void* __restrict__ ei) {
    unsigned e = blockIdx.x * blockDim.x + threadIdx.x;
    if (e >= (unsigned)EE) return;
    if (d_is64) {
        const long long* p = (const long long*)ei;
        d_row32[e] = (int)p[e];
        d_col32[e] = (int)p[(size_t)EE + e];
    } else {
        const int* p = (const int*)ei;
        d_row32[e] = p[e];
        d_col32[e] = p[EE + e];
    }
}

// ---------------- zero histogram ----------------
__global__ void k_zero() {
    unsigned i = blockIdx.x * blockDim.x + threadIdx.x;
    if (i < (unsigned)NN) d_cnt[i] = 0;
}

// ---------------- histogram by target (col) ----------------
__global__ void k_hist() {
    unsigned e = blockIdx.x * blockDim.x + threadIdx.x;
    if (e < (unsigned)EE) atomicAdd(&d_cnt[d_col32[e]], 1);
}

// ---------------- single-block scan: offsets, cursors, dis ----------------
__global__ __launch_bounds__(1024) void k_scan() {
    __shared__ int ssum[1024];
    int t = threadIdx.x;
    const int CH = (NN + 1023) / 1024;  // 98
    int lo = t * CH;
    int hi = lo + CH; if (hi > NN) hi = NN;
    int s = 0;
    for (int i = lo; i < hi; i++) s += d_cnt[i];
    ssum[t] = s;
    __syncthreads();
    for (int off = 1; off < 1024; off <<= 1) {
        int v = (t >= off) ? ssum[t - off] : 0;
        __syncthreads();
        ssum[t] += v;
        __syncthreads();
    }
    int run = (t == 0) ? 0 : ssum[t - 1];
    for (int i = lo; i < hi; i++) {
        int c = d_cnt[i];
        d_off[i] = run;
        d_cur[i] = run;
        d_dis[i] = rsqrtf((float)(c + 1));  // +1 self loop
        run += c;
    }
}

// ---------------- fill CSR ----------------
__global__ void k_fill() {
    unsigned e = blockIdx.x * blockDim.x + threadIdx.x;
    if (e >= (unsigned)EE) return;
    int c = d_col32[e];
    int p = atomicAdd(&d_cur[c], 1);
    d_erow[p] = d_row32[e];
}

// ---------------- GEMM1: g1 = dis * (x @ W1), [N,256]x[256,64] ----------------
__global__ __launch_bounds__(128) void k_gemm1(const float* __restrict__ x,
                                               const float* __restrict__ W1) {
    __shared__ float As[128][33];
    __shared__ float Bs[32][64];
    int t = threadIdx.x;
    int m0 = blockIdx.x * 128;
    int ty = t >> 3;
    int tx = t & 7;
    float acc[8][8];
#pragma unroll
    for (int i = 0; i < 8; i++)
#pragma unroll
        for (int j = 0; j < 8; j++) acc[i][j] = 0.f;

    for (int k0 = 0; k0 < IN_CH; k0 += 32) {
#pragma unroll
        for (int jj = 0; jj < 4; jj++) {
            int m = jj * 32 + (t >> 2);
            int kq = (t & 3) * 8;
            int gm = m0 + m;
            float4 v0, v1;
            if (gm < NN) {
                const float* src = x + (size_t)gm * IN_CH + k0 + kq;
                v0 = *(const float4*)src;
                v1 = *(const float4*)(src + 4);
            } else {
                v0 = make_float4(0.f, 0.f, 0.f, 0.f);
                v1 = v0;
            }
            As[m][kq + 0] = v0.x; As[m][kq + 1] = v0.y;
            As[m][kq + 2] = v0.z; As[m][kq + 3] = v0.w;
            As[m][kq + 4] = v1.x; As[m][kq + 5] = v1.y;
            As[m][kq + 6] = v1.z; As[m][kq + 7] = v1.w;
        }
#pragma unroll
        for (int jj = 0; jj < 4; jj++) {
            int idx = t + jj * 128;
            int k = idx >> 4;
            int q = (idx & 15) * 4;
            float4 w = *(const float4*)(W1 + (size_t)(k0 + k) * HID + q);
            Bs[k][q + 0] = w.x; Bs[k][q + 1] = w.y;
            Bs[k][q + 2] = w.z; Bs[k][q + 3] = w.w;
        }
        __syncthreads();
#pragma unroll
        for (int k = 0; k < 32; k++) {
            float a[8], b[8];
#pragma unroll
            for (int i = 0; i < 8; i++) a[i] = As[ty * 8 + i][k];
#pragma unroll
            for (int j = 0; j < 8; j++) b[j] = Bs[k][tx * 8 + j];
#pragma unroll
            for (int i = 0; i < 8; i++)
#pragma unroll
                for (int j = 0; j < 8; j++) acc[i][j] = fmaf(a[i], b[j], acc[i][j]);
        }
        __syncthreads();
    }
#pragma unroll
    for (int i = 0; i < 8; i++) {
        int m = m0 + ty * 8 + i;
        if (m < NN) {
            float s = d_dis[m];
#pragma unroll
            for (int j = 0; j < 8; j += 4) {
                float4 v = make_float4(s * acc[i][j], s * acc[i][j + 1],
                                       s * acc[i][j + 2], s * acc[i][j + 3]);
                *(float4*)&d_g1[(size_t)m * HID + tx * 8 + j] = v;
            }
        }
    }
}

// ---------------- agg1 fused: gather g1 + self + ELU + GEMM2 -> g2 ----------------
// 1 warp per node; lane owns features 2*lane, 2*lane+1. W2 in shared.
__global__ __launch_bounds__(256) void k_agg1(const float* __restrict__ b1,
                                              const float* __restrict__ W2) {
    __shared__ float sW[64][32];   // W2
    __shared__ float sh[8][64];    // h per warp
    int t = threadIdx.x;
    int warp = t >> 5;
    int lane = t & 31;
    // load W2: 2048 floats, 8 per thread
#pragma unroll
    for (int jj = 0; jj < 8; jj++) {
        int idx = t + jj * 256;
        sW[idx >> 5][idx & 31] = W2[idx];
    }
    __syncthreads();

    int v = blockIdx.x * 8 + warp;
    if (v >= NN) return;

    int start = d_off[v];
    int cnt = d_cnt[v];
    // self term
    float2 acc = *(const float2*)(d_g1 + (size_t)v * HID + lane * 2);

    for (int base = 0; base < cnt; base += 32) {
        int nb = cnt - base; if (nb > 32) nb = 32;
        int er = (lane < nb) ? d_erow[start + base + lane] : 0;
        int nb4 = (nb + 3) & ~3;
        for (int j = 0; j < nb4; j += 4) {
#pragma unroll
            for (int u = 0; u < 4; u++) {
                int jj = j + u;
                int r = __shfl_sync(0xffffffffu, er, jj & 31);
                bool pv = jj < nb;
                r = pv ? r : 0;
                float2 g = *(const float2*)(d_g1 + (size_t)r * HID + lane * 2);
                if (pv) { acc.x += g.x; acc.y += g.y; }
            }
        }
    }

    float s = d_dis[v];
    float p0 = s * acc.x + b1[lane * 2];
    float p1 = s * acc.y + b1[lane * 2 + 1];
    float h0 = p0 > 0.f ? p0 : expm1f(p0);
    float h1 = p1 > 0.f ? p1 : expm1f(p1);
    sh[warp][lane * 2] = h0;
    sh[warp][lane * 2 + 1] = h1;
    __syncwarp();

    // GEMM2 for this node: out[o=lane] = sum_f h[f] * W2[f][o]
    float o_acc = 0.f;
#pragma unroll
    for (int f = 0; f < 64; f++) o_acc = fmaf(sh[warp][f], sW[f][lane], o_acc);
    d_g2[(size_t)v * OUTC + lane] = s * o_acc;
}

// ---------------- agg2 fused: gather g2 + self + ELU + dot(Wc) -> out ----------------
__global__ __launch_bounds__(256) void k_agg2(const float* __restrict__ b2,
                                              const float* __restrict__ Wc,
                                              const float* __restrict__ bc,
                                              float* __restrict__ out) {
    int t = threadIdx.x;
    int warp = t >> 5;
    int lane = t & 31;
    int v = blockIdx.x * 8 + warp;
    if (v >= NN) return;

    int start = d_off[v];
    int cnt = d_cnt[v];
    float acc = d_g2[(size_t)v * OUTC + lane];  // self

    for (int base = 0; base < cnt; base += 32) {
        int nb = cnt - base; if (nb > 32) nb = 32;
        int er = (lane < nb) ? d_erow[start + base + lane] : 0;
        int nb4 = (nb + 3) & ~3;
        for (int j = 0; j < nb4; j += 4) {
#pragma unroll
            for (int u = 0; u < 4; u++) {
                int jj = j + u;
                int r = __shfl_sync(0xffffffffu, er, jj & 31);
                bool pv = jj < nb;
                r = pv ? r : 0;
                float g = d_g2[(size_t)r * OUTC + lane];
                if (pv) acc += g;
            }
        }
    }

    float pre = d_dis[v] * acc + b2[lane];
    float h = pre > 0.f ? pre : expm1f(pre);
    float p = h * Wc[lane];
#pragma unroll
    for (int off = 16; off; off >>= 1) p += __shfl_xor_sync(0xffffffffu, p, off);
    if (lane == 0) out[v] = p + bc[0];
}

// ---------------- launch ----------------
extern "C" void kernel_launch(void* const* d_in, const int* in_sizes, int n_in,
                              void* d_out, int out_size) {
    const float* x  = (const float*)d_in[0];
    const void*  ei = d_in[1];                 // [2,E], int32 or int64 (auto-detected)
    const float* W1 = (const float*)d_in[2];
    const float* b1 = (const float*)d_in[3];
    const float* W2 = (const float*)d_in[4];
    const float* b2 = (const float*)d_in[5];
    const float* Wc = (const float*)d_in[6];
    const float* bc = (const float*)d_in[7];
    float*       out = (float*)d_out;

    k_detect<<<1, 32>>>((const int*)ei);
    k_cvt<<<(EE + 255) / 256, 256>>>(ei);
    k_zero<<<(NN + 255) / 256, 256>>>();
    k_hist<<<(EE + 255) / 256, 256>>>();
    k_scan<<<1, 1024>>>();
    k_fill<<<(EE + 255) / 256, 256>>>();
    k_gemm1<<<(NN + 127) / 128, 128>>>(x, W1);
    k_agg1<<<(NN + 7) / 8, 256>>>(b1, W2);
    k_agg2<<<(NN + 7) / 8, 256>>>(b2, Wc, bc, out);
}

// round 9
// speedup vs baseline: 1.0315x; 1.0315x over previous
#include <cuda_runtime.h>
#include <cstdint>

#define NN 100000
#define EE 3200000
#define IN_CH 256
#define HID 64
#define OUTC 32

// ---------------- scratch (no allocations allowed) ----------------
__device__ int   d_is64;                      // 1 if edge_index is int64, else 0
__device__ __align__(16) int   d_cnt[NN];     // in-degree (edges only)
__device__ __align__(16) int   d_off[NN];     // CSR start offsets
__device__ __align__(16) int   d_cur[NN];     // fill cursors
__device__ __align__(16) int   d_erow[EE];    // CSR payload: source node per edge
__device__ __align__(16) float d_dis[NN];
__device__ __align__(16) float d_g1[(size_t)NN * HID];   // dis * (x @ W1)
__device__ __align__(16) float d_g2[(size_t)NN * OUTC];  // dis * (h1 @ W2)

// ---------------- packed fp32x2 helpers (sm_100+: FFMA2) ----------------
__device__ __forceinline__ unsigned long long pack2(float x, float y) {
    unsigned long long r;
    asm("mov.b64 %0, {%1, %2};" : "=l"(r) : "f"(x), "f"(y));
    return r;
}
__device__ __forceinline__ unsigned long long fma2(unsigned long long a,
                                                   unsigned long long b,
                                                   unsigned long long c) {
    unsigned long long d;
    asm("fma.rn.f32x2 %0, %1, %2, %3;" : "=l"(d) : "l"(a), "l"(b), "l"(c));
    return d;
}
__device__ __forceinline__ void unpack2(unsigned long long v, float& x, float& y) {
    asm("mov.b64 {%0, %1}, %2;" : "=f"(x), "=f"(y) : "l"(v));
}

// ---------------- dtype detector: int64 edge_index has all-zero odd words ----------------
__global__ void k_detect(const int* __restrict__ ei_w) {
    int lane = threadIdx.x;  // one warp
    int nz = 0;
#pragma unroll
    for (int j = 0; j < 8; j++) {
        long long k = (long long)(lane * 8 + j) * (EE / 512);  // < EE/2
        nz |= ei_w[2 * k + 1];
    }
    unsigned any = __ballot_sync(0xffffffffu, nz != 0);
    if (lane == 0) d_is64 = (any == 0u) ? 1 : 0;
}

// ---------------- zero histogram ----------------
__global__ void k_zero() {
    unsigned i = blockIdx.x * blockDim.x + threadIdx.x;
    if (i < (unsigned)NN) d_cnt[i] = 0;
}

// ---------------- histogram by target (col), reading edge_index directly ----------------
__global__ void k_hist(const void* __restrict__ ei) {
    unsigned e = blockIdx.x * blockDim.x + threadIdx.x;
    if (e >= (unsigned)EE) return;
    int c = d_is64 ? (int)((const long long*)ei)[(size_t)EE + e]
                   : ((const int*)ei)[EE + e];
    atomicAdd(&d_cnt[c], 1);
}

// ---------------- single-block scan: offsets, cursors, dis ----------------
__global__ __launch_bounds__(1024) void k_scan() {
    __shared__ int ssum[1024];
    int t = threadIdx.x;
    const int CH = (NN + 1023) / 1024;  // 98
    int lo = t * CH;
    int hi = lo + CH; if (hi > NN) hi = NN;
    int s = 0;
    for (int i = lo; i < hi; i++) s += d_cnt[i];
    ssum[t] = s;
    __syncthreads();
    for (int off = 1; off < 1024; off <<= 1) {
        int v = (t >= off) ? ssum[t - off] : 0;
        __syncthreads();
        ssum[t] += v;
        __syncthreads();
    }
    int run = (t == 0) ? 0 : ssum[t - 1];
    for (int i = lo; i < hi; i++) {
        int c = d_cnt[i];
        d_off[i] = run;
        d_cur[i] = run;
        d_dis[i] = rsqrtf((float)(c + 1));  // +1 self loop
        run += c;
    }
}

// ---------------- fill CSR, reading edge_index directly ----------------
__global__ void k_fill(const void* __restrict__ ei) {
    unsigned e = blockIdx.x * blockDim.x + threadIdx.x;
    if (e >= (unsigned)EE) return;
    int r, c;
    if (d_is64) {
        const long long* p = (const long long*)ei;
        r = (int)p[e];
        c = (int)p[(size_t)EE + e];
    } else {
        const int* p = (const int*)ei;
        r = p[e];
        c = p[EE + e];
    }
    int pos = atomicAdd(&d_cur[c], 1);
    d_erow[pos] = r;
}

// ---------------- GEMM1: g1 = dis * (x @ W1), packed f32x2 FMAs ----------------
__global__ __launch_bounds__(128) void k_gemm1(const float* __restrict__ x,
                                               const float* __restrict__ W1) {
    __shared__ float As[128][33];
    __shared__ float Bs[32][64];
    int t = threadIdx.x;
    int m0 = blockIdx.x * 128;
    int ty = t >> 3;          // 0..15
    int tx = t & 7;           // 0..7
    unsigned long long acc[8][4];
    const unsigned long long z = pack2(0.f, 0.f);
#pragma unroll
    for (int i = 0; i < 8; i++)
#pragma unroll
        for (int j = 0; j < 4; j++) acc[i][j] = z;

    for (int k0 = 0; k0 < IN_CH; k0 += 32) {
#pragma unroll
        for (int jj = 0; jj < 4; jj++) {
            int m = jj * 32 + (t >> 2);
            int kq = (t & 3) * 8;
            int gm = m0 + m;
            float4 v0, v1;
            if (gm < NN) {
                const float* src = x + (size_t)gm * IN_CH + k0 + kq;
                v0 = *(const float4*)src;
                v1 = *(const float4*)(src + 4);
            } else {
                v0 = make_float4(0.f, 0.f, 0.f, 0.f);
                v1 = v0;
            }
            As[m][kq + 0] = v0.x; As[m][kq + 1] = v0.y;
            As[m][kq + 2] = v0.z; As[m][kq + 3] = v0.w;
            As[m][kq + 4] = v1.x; As[m][kq + 5] = v1.y;
            As[m][kq + 6] = v1.z; As[m][kq + 7] = v1.w;
        }
#pragma unroll
        for (int jj = 0; jj < 4; jj++) {
            int idx = t + jj * 128;
            int k = idx >> 4;
            int q = (idx & 15) * 4;
            float4 w = *(const float4*)(W1 + (size_t)(k0 + k) * HID + q);
            Bs[k][q + 0] = w.x; Bs[k][q + 1] = w.y;
            Bs[k][q + 2] = w.z; Bs[k][q + 3] = w.w;
        }
        __syncthreads();
#pragma unroll
        for (int k = 0; k < 32; k++) {
            unsigned long long a2[8], b2[4];
#pragma unroll
            for (int i = 0; i < 8; i++) {
                float a = As[ty * 8 + i][k];
                a2[i] = pack2(a, a);
            }
#pragma unroll
            for (int j = 0; j < 4; j++) {
                float2 b = *(const float2*)&Bs[k][tx * 8 + j * 2];
                b2[j] = pack2(b.x, b.y);
            }
#pragma unroll
            for (int i = 0; i < 8; i++)
#pragma unroll
                for (int j = 0; j < 4; j++) acc[i][j] = fma2(a2[i], b2[j], acc[i][j]);
        }
        __syncthreads();
    }
#pragma unroll
    for (int i = 0; i < 8; i++) {
        int m = m0 + ty * 8 + i;
        if (m < NN) {
            float s = d_dis[m];
            float r[8];
#pragma unroll
            for (int j = 0; j < 4; j++) unpack2(acc[i][j], r[j * 2], r[j * 2 + 1]);
            float4 v0 = make_float4(s * r[0], s * r[1], s * r[2], s * r[3]);
            float4 v1 = make_float4(s * r[4], s * r[5], s * r[6], s * r[7]);
            *(float4*)&d_g1[(size_t)m * HID + tx * 8] = v0;
            *(float4*)&d_g1[(size_t)m * HID + tx * 8 + 4] = v1;
        }
    }
}

// ---------------- agg1 fused: gather g1 + self + ELU + GEMM2 -> g2 ----------------
// 1 warp per node; lane owns features 2*lane, 2*lane+1. W2 in shared.
__global__ __launch_bounds__(256) void k_agg1(const float* __restrict__ b1,
                                              const float* __restrict__ W2) {
    __shared__ float sW[64][32];   // W2
    __shared__ float sh[8][64];    // h per warp
    int t = threadIdx.x;
    int warp = t >> 5;
    int lane = t & 31;
    ((float4*)sW)[t] = ((const float4*)W2)[t];
    ((float4*)sW)[t + 256] = ((const float4*)W2)[t + 256];
    __syncthreads();

    int v = blockIdx.x * 8 + warp;
    if (v >= NN) return;

    int start = d_off[v];
    int cnt = d_cnt[v];
    float2 acc = *(const float2*)(d_g1 + (size_t)v * HID + lane * 2);  // self

    for (int base = 0; base < cnt; base += 32) {
        int nb = cnt - base; if (nb > 32) nb = 32;
        int er = (lane < nb) ? d_erow[start + base + lane] : 0;
        int nb8 = (nb + 7) & ~7;
        for (int j = 0; j < nb8; j += 8) {
            // 8 independent gathers in flight
            float2 g[8];
            bool pv[8];
#pragma unroll
            for (int u = 0; u < 8; u++) {
                int jj = j + u;
                int r = __shfl_sync(0xffffffffu, er, jj & 31);
                pv[u] = jj < nb;
                r = pv[u] ? r : v;  // harmless in-range dummy
                g[u] = *(const float2*)(d_g1 + (size_t)r * HID + lane * 2);
            }
#pragma unroll
            for (int u = 0; u < 8; u++)
                if (pv[u]) { acc.x += g[u].x; acc.y += g[u].y; }
        }
    }

    float s = d_dis[v];
    float p0 = s * acc.x + b1[lane * 2];
    float p1 = s * acc.y + b1[lane * 2 + 1];
    float h0 = p0 > 0.f ? p0 : expm1f(p0);
    float h1 = p1 > 0.f ? p1 : expm1f(p1);
    sh[warp][lane * 2] = h0;
    sh[warp][lane * 2 + 1] = h1;
    __syncwarp();

    // GEMM2 for this node: out[o=lane] = sum_f h[f] * W2[f][o]
    float o_acc = 0.f;
#pragma unroll
    for (int f = 0; f < 64; f++) o_acc = fmaf(sh[warp][f], sW[f][lane], o_acc);
    d_g2[(size_t)v * OUTC + lane] = s * o_acc;
}

// ---------------- agg2 fused: gather g2 + self + ELU + dot(Wc) -> out ----------------
__global__ __launch_bounds__(256) void k_agg2(const float* __restrict__ b2,
                                              const float* __restrict__ Wc,
                                              const float* __restrict__ bc,
                                              float* __restrict__ out) {
    int t = threadIdx.x;
    int warp = t >> 5;
    int lane = t & 31;
    int v = blockIdx.x * 8 + warp;
    if (v >= NN) return;

    int start = d_off[v];
    int cnt = d_cnt[v];
    float acc = d_g2[(size_t)v * OUTC + lane];  // self

    for (int base = 0; base < cnt; base += 32) {
        int nb = cnt - base; if (nb > 32) nb = 32;
        int er = (lane < nb) ? d_erow[start + base + lane] : 0;
        int nb8 = (nb + 7) & ~7;
        for (int j = 0; j < nb8; j += 8) {
            float g[8];
            bool pv[8];
#pragma unroll
            for (int u = 0; u < 8; u++) {
                int jj = j + u;
                int r = __shfl_sync(0xffffffffu, er, jj & 31);
                pv[u] = jj < nb;
                r = pv[u] ? r : v;
                g[u] = d_g2[(size_t)r * OUTC + lane];
            }
#pragma unroll
            for (int u = 0; u < 8; u++)
                if (pv[u]) acc += g[u];
        }
    }

    float pre = d_dis[v] * acc + b2[lane];
    float h = pre > 0.f ? pre : expm1f(pre);
    float p = h * Wc[lane];
#pragma unroll
    for (int off = 16; off; off >>= 1) p += __shfl_xor_sync(0xffffffffu, p, off);
    if (lane == 0) out[v] = p + bc[0];
}

// ---------------- launch ----------------
extern "C" void kernel_launch(void* const* d_in, const int* in_sizes, int n_in,
                              void* d_out, int out_size) {
    const float* x  = (const float*)d_in[0];
    const void*  ei = d_in[1];                 // [2,E], int32 or int64 (auto-detected)
    const float* W1 = (const float*)d_in[2];
    const float* b1 = (const float*)d_in[3];
    const float* W2 = (const float*)d_in[4];
    const float* b2 = (const float*)d_in[5];
    const float* Wc = (const float*)d_in[6];
    const float* bc = (const float*)d_in[7];
    float*       out = (float*)d_out;

    k_detect<<<1, 32>>>((const int*)ei);
    k_zero<<<(NN + 255) / 256, 256>>>();
    k_hist<<<(EE + 255) / 256, 256>>>(ei);
    k_scan<<<1, 1024>>>();
    k_fill<<<(EE + 255) / 256, 256>>>(ei);
    k_gemm1<<<(NN + 127) / 128, 128>>>(x, W1);
    k_agg1<<<(NN + 7) / 8, 256>>>(b1, W2);
    k_agg2<<<(NN + 7) / 8, 256>>>(b2, Wc, bc, out);
}

// round 10
// speedup vs baseline: 1.6800x; 1.6287x over previous
#include <cuda_runtime.h>
#include <cstdint>

#define NN 100000
#define EE 3200000
#define IN_CH 256
#define HID 64
#define OUTC 32

#define SCAN_B 1024
#define NBLK ((NN + SCAN_B - 1) / SCAN_B)   // 98

// ---------------- scratch (no allocations allowed) ----------------
__device__ int   d_is64;                      // 1 if edge_index is int64, else 0
__device__ __align__(16) int   d_cnt[NN];     // in-degree (edges only)
__device__ __align__(16) int   d_off[NN];     // CSR start offsets
__device__ __align__(16) int   d_cur[NN];     // fill cursors
__device__ __align__(16) int   d_erow[EE];    // CSR payload: source node per edge
__device__ __align__(16) int   d_bsum[NBLK];  // per-block count sums
__device__ __align__(16) int   d_boff[NBLK];  // scanned block offsets
__device__ __align__(16) float d_dis[NN];
__device__ __align__(16) float d_g1[(size_t)NN * HID];   // dis * (x @ W1)
__device__ __align__(16) float d_g2[(size_t)NN * OUTC];  // dis * (h1 @ W2)

// ---------------- packed fp32x2 helpers (sm_100+: FFMA2) ----------------
__device__ __forceinline__ unsigned long long pack2(float x, float y) {
    unsigned long long r;
    asm("mov.b64 %0, {%1, %2};" : "=l"(r) : "f"(x), "f"(y));
    return r;
}
__device__ __forceinline__ unsigned long long fma2(unsigned long long a,
                                                   unsigned long long b,
                                                   unsigned long long c) {
    unsigned long long d;
    asm("fma.rn.f32x2 %0, %1, %2, %3;" : "=l"(d) : "l"(a), "l"(b), "l"(c));
    return d;
}
__device__ __forceinline__ void unpack2(unsigned long long v, float& x, float& y) {
    asm("mov.b64 {%0, %1}, %2;" : "=f"(x), "=f"(y) : "l"(v));
}

// ---------------- dtype detector: int64 edge_index has all-zero odd words ----------------
__global__ void k_detect(const int* __restrict__ ei_w) {
    int lane = threadIdx.x;  // one warp
    int nz = 0;
#pragma unroll
    for (int j = 0; j < 8; j++) {
        long long k = (long long)(lane * 8 + j) * (EE / 512);  // < EE/2
        nz |= ei_w[2 * k + 1];
    }
    unsigned any = __ballot_sync(0xffffffffu, nz != 0);
    if (lane == 0) d_is64 = (any == 0u) ? 1 : 0;
}

// ---------------- zero histogram ----------------
__global__ void k_zero() {
    unsigned i = blockIdx.x * blockDim.x + threadIdx.x;
    if (i < (unsigned)NN) d_cnt[i] = 0;
}

// ---------------- histogram by target (col), reading edge_index directly ----------------
__global__ void k_hist(const void* __restrict__ ei) {
    unsigned e = blockIdx.x * blockDim.x + threadIdx.x;
    if (e >= (unsigned)EE) return;
    int c = d_is64 ? (int)((const long long*)ei)[(size_t)EE + e]
                   : ((const int*)ei)[EE + e];
    atomicAdd(&d_cnt[c], 1);
}

// ---------------- scan phase 1: per-block sums ----------------
__global__ __launch_bounds__(SCAN_B) void k_bsum() {
    __shared__ int sred[SCAN_B / 32];
    int t = threadIdx.x;
    unsigned i = blockIdx.x * SCAN_B + t;
    int c = (i < (unsigned)NN) ? d_cnt[i] : 0;
    int w = c;
#pragma unroll
    for (int off = 16; off; off >>= 1) w += __shfl_xor_sync(0xffffffffu, w, off);
    if ((t & 31) == 0) sred[t >> 5] = w;
    __syncthreads();
    if (t < 32) {
        int s = (t < SCAN_B / 32) ? sred[t] : 0;
#pragma unroll
        for (int off = 16; off; off >>= 1) s += __shfl_xor_sync(0xffffffffu, s, off);
        if (t == 0) d_bsum[blockIdx.x] = s;
    }
}

// ---------------- scan phase 2: exclusive scan of 98 block sums ----------------
__global__ void k_bscan() {
    __shared__ int sv[128];
    int t = threadIdx.x;  // 128 threads
    sv[t] = (t < NBLK) ? d_bsum[t] : 0;
    __syncthreads();
#pragma unroll
    for (int off = 1; off < 128; off <<= 1) {
        int v = (t >= off) ? sv[t - off] : 0;
        __syncthreads();
        sv[t] += v;
        __syncthreads();
    }
    if (t < NBLK) d_boff[t] = (t == 0) ? 0 : sv[t - 1];
}

// ---------------- scan phase 3: intra-block exclusive scan + finalize ----------------
__global__ __launch_bounds__(SCAN_B) void k_off() {
    __shared__ int sv[SCAN_B];
    __shared__ int swsum[SCAN_B / 32];
    int t = threadIdx.x;
    int lane = t & 31;
    int wp = t >> 5;
    unsigned i = blockIdx.x * SCAN_B + t;
    int c = (i < (unsigned)NN) ? d_cnt[i] : 0;
    // warp-level inclusive scan
    int s = c;
#pragma unroll
    for (int off = 1; off < 32; off <<= 1) {
        int v = __shfl_up_sync(0xffffffffu, s, off);
        if (lane >= off) s += v;
    }
    if (lane == 31) swsum[wp] = s;
    __syncthreads();
    if (t < 32) {
        int ws = (t < SCAN_B / 32) ? swsum[t] : 0;
#pragma unroll
        for (int off = 1; off < 32; off <<= 1) {
            int v = __shfl_up_sync(0xffffffffu, ws, off);
            if ((t & 31) >= off) ws += v;
        }
        if (t < SCAN_B / 32) swsum[t] = ws;
    }
    __syncthreads();
    int excl = s - c + (wp ? swsum[wp - 1] : 0) + d_boff[blockIdx.x];
    if (i < (unsigned)NN) {
        d_off[i] = excl;
        d_cur[i] = excl;
        d_dis[i] = rsqrtf((float)(c + 1));  // +1 self loop
    }
    (void)sv;
}

// ---------------- fill CSR, reading edge_index directly ----------------
__global__ void k_fill(const void* __restrict__ ei) {
    unsigned e = blockIdx.x * blockDim.x + threadIdx.x;
    if (e >= (unsigned)EE) return;
    int r, c;
    if (d_is64) {
        const long long* p = (const long long*)ei;
        r = (int)p[e];
        c = (int)p[(size_t)EE + e];
    } else {
        const int* p = (const int*)ei;
        r = p[e];
        c = p[EE + e];
    }
    int pos = atomicAdd(&d_cur[c], 1);
    d_erow[pos] = r;
}

// ---------------- GEMM1: g1 = dis * (x @ W1), packed f32x2 FMAs ----------------
__global__ __launch_bounds__(128) void k_gemm1(const float* __restrict__ x,
                                               const float* __restrict__ W1) {
    __shared__ float As[128][33];
    __shared__ float Bs[32][64];
    int t = threadIdx.x;
    int m0 = blockIdx.x * 128;
    int ty = t >> 3;          // 0..15
    int tx = t & 7;           // 0..7
    unsigned long long acc[8][4];
    const unsigned long long z = pack2(0.f, 0.f);
#pragma unroll
    for (int i = 0; i < 8; i++)
#pragma unroll
        for (int j = 0; j < 4; j++) acc[i][j] = z;

    for (int k0 = 0; k0 < IN_CH; k0 += 32) {
#pragma unroll
        for (int jj = 0; jj < 4; jj++) {
            int m = jj * 32 + (t >> 2);
            int kq = (t & 3) * 8;
            int gm = m0 + m;
            float4 v0, v1;
            if (gm < NN) {
                const float* src = x + (size_t)gm * IN_CH + k0 + kq;
                v0 = *(const float4*)src;
                v1 = *(const float4*)(src + 4);
            } else {
                v0 = make_float4(0.f, 0.f, 0.f, 0.f);
                v1 = v0;
            }
            As[m][kq + 0] = v0.x; As[m][kq + 1] = v0.y;
            As[m][kq + 2] = v0.z; As[m][kq + 3] = v0.w;
            As[m][kq + 4] = v1.x; As[m][kq + 5] = v1.y;
            As[m][kq + 6] = v1.z; As[m][kq + 7] = v1.w;
        }
#pragma unroll
        for (int jj = 0; jj < 4; jj++) {
            int idx = t + jj * 128;
            int k = idx >> 4;
            int q = (idx & 15) * 4;
            float4 w = *(const float4*)(W1 + (size_t)(k0 + k) * HID + q);
            Bs[k][q + 0] = w.x; Bs[k][q + 1] = w.y;
            Bs[k][q + 2] = w.z; Bs[k][q + 3] = w.w;
        }
        __syncthreads();
#pragma unroll
        for (int k = 0; k < 32; k++) {
            unsigned long long a2[8], b2[4];
#pragma unroll
            for (int i = 0; i < 8; i++) {
                float a = As[ty * 8 + i][k];
                a2[i] = pack2(a, a);
            }
#pragma unroll
            for (int j = 0; j < 4; j++) {
                float2 b = *(const float2*)&Bs[k][tx * 8 + j * 2];
                b2[j] = pack2(b.x, b.y);
            }
#pragma unroll
            for (int i = 0; i < 8; i++)
#pragma unroll
                for (int j = 0; j < 4; j++) acc[i][j] = fma2(a2[i], b2[j], acc[i][j]);
        }
        __syncthreads();
    }
#pragma unroll
    for (int i = 0; i < 8; i++) {
        int m = m0 + ty * 8 + i;
        if (m < NN) {
            float s = d_dis[m];
            float r[8];
#pragma unroll
            for (int j = 0; j < 4; j++) unpack2(acc[i][j], r[j * 2], r[j * 2 + 1]);
            float4 v0 = make_float4(s * r[0], s * r[1], s * r[2], s * r[3]);
            float4 v1 = make_float4(s * r[4], s * r[5], s * r[6], s * r[7]);
            *(float4*)&d_g1[(size_t)m * HID + tx * 8] = v0;
            *(float4*)&d_g1[(size_t)m * HID + tx * 8 + 4] = v1;
        }
    }
}

// ---------------- agg1 fused: gather g1 + self + ELU + GEMM2 -> g2 ----------------
// 1 warp per node; lane owns features 2*lane, 2*lane+1. W2 in shared.
__global__ __launch_bounds__(256) void k_agg1(const float* __restrict__ b1,
                                              const float* __restrict__ W2) {
    __shared__ float sW[64][32];   // W2
    __shared__ float sh[8][64];    // h per warp
    int t = threadIdx.x;
    int warp = t >> 5;
    int lane = t & 31;
    ((float4*)sW)[t] = ((const float4*)W2)[t];
    ((float4*)sW)[t + 256] = ((const float4*)W2)[t + 256];
    __syncthreads();

    int v = blockIdx.x * 8 + warp;
    if (v >= NN) return;

    int start = d_off[v];
    int cnt = d_cnt[v];
    float2 acc = *(const float2*)(d_g1 + (size_t)v * HID + lane * 2);  // self

    for (int base = 0; base < cnt; base += 32) {
        int nb = cnt - base; if (nb > 32) nb = 32;
        int er = (lane < nb) ? d_erow[start + base + lane] : 0;
        int nb8 = (nb + 7) & ~7;
        for (int j = 0; j < nb8; j += 8) {
            // 8 independent gathers in flight
            float2 g[8];
            bool pv[8];
#pragma unroll
            for (int u = 0; u < 8; u++) {
                int jj = j + u;
                int r = __shfl_sync(0xffffffffu, er, jj & 31);
                pv[u] = jj < nb;
                r = pv[u] ? r : v;  // harmless in-range dummy
                g[u] = *(const float2*)(d_g1 + (size_t)r * HID + lane * 2);
            }
#pragma unroll
            for (int u = 0; u < 8; u++)
                if (pv[u]) { acc.x += g[u].x; acc.y += g[u].y; }
        }
    }

    float s = d_dis[v];
    float p0 = s * acc.x + b1[lane * 2];
    float p1 = s * acc.y + b1[lane * 2 + 1];
    float h0 = p0 > 0.f ? p0 : expm1f(p0);
    float h1 = p1 > 0.f ? p1 : expm1f(p1);
    sh[warp][lane * 2] = h0;
    sh[warp][lane * 2 + 1] = h1;
    __syncwarp();

    // GEMM2 for this node: out[o=lane] = sum_f h[f] * W2[f][o]
    float o_acc = 0.f;
#pragma unroll
    for (int f = 0; f < 64; f++) o_acc = fmaf(sh[warp][f], sW[f][lane], o_acc);
    d_g2[(size_t)v * OUTC + lane] = s * o_acc;
}

// ---------------- agg2 fused: gather g2 + self + ELU + dot(Wc) -> out ----------------
__global__ __launch_bounds__(256) void k_agg2(const float* __restrict__ b2,
                                              const float* __restrict__ Wc,
                                              const float* __restrict__ bc,
                                              float* __restrict__ out) {
    int t = threadIdx.x;
    int warp = t >> 5;
    int lane = t & 31;
    int v = blockIdx.x * 8 + warp;
    if (v >= NN) return;

    int start = d_off[v];
    int cnt = d_cnt[v];
    float acc = d_g2[(size_t)v * OUTC + lane];  // self

    for (int base = 0; base < cnt; base += 32) {
        int nb = cnt - base; if (nb > 32) nb = 32;
        int er = (lane < nb) ? d_erow[start + base + lane] : 0;
        int nb8 = (nb + 7) & ~7;
        for (int j = 0; j < nb8; j += 8) {
            float g[8];
            bool pv[8];
#pragma unroll
            for (int u = 0; u < 8; u++) {
                int jj = j + u;
                int r = __shfl_sync(0xffffffffu, er, jj & 31);
                pv[u] = jj < nb;
                r = pv[u] ? r : v;
                g[u] = d_g2[(size_t)r * OUTC + lane];
            }
#pragma unroll
            for (int u = 0; u < 8; u++)
                if (pv[u]) acc += g[u];
        }
    }

    float pre = d_dis[v] * acc + b2[lane];
    float h = pre > 0.f ? pre : expm1f(pre);
    float p = h * Wc[lane];
#pragma unroll
    for (int off = 16; off; off >>= 1) p += __shfl_xor_sync(0xffffffffu, p, off);
    if (lane == 0) out[v] = p + bc[0];
}

// ---------------- launch ----------------
extern "C" void kernel_launch(void* const* d_in, const int* in_sizes, int n_in,
                              void* d_out, int out_size) {
    const float* x  = (const float*)d_in[0];
    const void*  ei = d_in[1];                 // [2,E], int32 or int64 (auto-detected)
    const float* W1 = (const float*)d_in[2];
    const float* b1 = (const float*)d_in[3];
    const float* W2 = (const float*)d_in[4];
    const float* b2 = (const float*)d_in[5];
    const float* Wc = (const float*)d_in[6];
    const float* bc = (const float*)d_in[7];
    float*       out = (float*)d_out;

    k_detect<<<1, 32>>>((const int*)ei);
    k_zero<<<(NN + 255) / 256, 256>>>();
    k_hist<<<(EE + 255) / 256, 256>>>(ei);
    k_bsum<<<NBLK, SCAN_B>>>();
    k_bscan<<<1, 128>>>();
    k_off<<<NBLK, SCAN_B>>>();
    k_fill<<<(EE + 255) / 256, 256>>>(ei);
    k_gemm1<<<(NN + 127) / 128, 128>>>(x, W1);
    k_agg1<<<(NN + 7) / 8, 256>>>(b1, W2);
    k_agg2<<<(NN + 7) / 8, 256>>>(b2, Wc, bc, out);
}